// round 7
// baseline (speedup 1.0000x reference)
#include <cuda_runtime.h>
#include <cuda_fp16.h>
#include <cstdint>
#include <math.h>

#define NN   100000
#define EE   1600000
#define ENC  128
#define PI_  98
#define KIN  226          // ENC + PI
#define KCH  240          // KIN padded to multiple of 16
#define MH   512          // 4 stacked [*,128] outputs (stage 1)
#define EMB  128
#define NB_SCAN 98        // ceil(NN/1024)

// ---------------- scratch (static device globals; no allocation) ----------------
__device__ __half   g_xh [(size_t)NN * KCH];     // concat(x,d2an) fp16
__device__ __half   g_wh1[MH * KCH];             // stage-1 fused weights fp16
__device__ __half   g_wz [2 * 128 * 256];        // stage-2 weights [y][m][k]: y0=[W3a|W3b], y1=[W4a|W4b]
__device__ __half   g_xmh[(size_t)NN * ENC];     // stage-1 result fp16
__device__ __half2  g_hh [(size_t)NN * (MH/2)];  // stage-1 GEMM output h (fp16)
__device__ __half   g_agg[(size_t)NN * 512];     // stage-2 pre-agg [A0|B0|A1|B1]
__device__ __half   g_c12[(size_t)NN * 256];     // stage-2 relu'd halves

// CSR (per edge set)
__device__ int     g_cnt   [2][NN];
__device__ int     g_rowptr[2][NN + 1];
__device__ int     g_cur   [2][NN];
__device__ int     g_bsum  [2][NB_SCAN];
__device__ float   g_dis   [2][NN];
__device__ int4    g_epack [2][EE];              // {src, dn(bits), einv(bits), 0}

// ---------------- mma helpers ----------------
__device__ __forceinline__ void ldsm4(unsigned &r0, unsigned &r1, unsigned &r2, unsigned &r3,
                                      unsigned addr) {
    asm volatile("ldmatrix.sync.aligned.m8n8.x4.shared.b16 {%0,%1,%2,%3}, [%4];"
                 : "=r"(r0), "=r"(r1), "=r"(r2), "=r"(r3) : "r"(addr));
}
__device__ __forceinline__ void ldsm2(unsigned &r0, unsigned &r1, unsigned addr) {
    asm volatile("ldmatrix.sync.aligned.m8n8.x2.shared.b16 {%0,%1}, [%2];"
                 : "=r"(r0), "=r"(r1) : "r"(addr));
}
__device__ __forceinline__ void mma16816(float &c0, float &c1, float &c2, float &c3,
                                         unsigned a0, unsigned a1, unsigned a2, unsigned a3,
                                         unsigned b0, unsigned b1) {
    asm volatile("mma.sync.aligned.m16n8k16.row.col.f32.f16.f16.f32 "
                 "{%0,%1,%2,%3}, {%4,%5,%6,%7}, {%8,%9}, {%0,%1,%2,%3};"
                 : "+f"(c0), "+f"(c1), "+f"(c2), "+f"(c3)
                 : "r"(a0), "r"(a1), "r"(a2), "r"(a3), "r"(b0), "r"(b1));
}

// ---------------- CSR build ----------------
__global__ void k_zero_cnt() {
    int i = blockIdx.x * blockDim.x + threadIdx.x;
    if (i < NN) { g_cnt[0][i] = 0; g_cnt[1][i] = 0; }
}

__global__ void k_hist(const int* __restrict__ ei0, const int* __restrict__ ei1) {
    int e = blockIdx.x * blockDim.x + threadIdx.x;
    if (e < EE) {
        atomicAdd(&g_cnt[0][ei0[EE + e]], 1);
        atomicAdd(&g_cnt[1][ei1[EE + e]], 1);
    }
}

__global__ void k_dis_k() {
    int i = blockIdx.x * blockDim.x + threadIdx.x;
    if (i < NN) {
        g_dis[0][i] = rsqrtf((float)(g_cnt[0][i] + 1));   // +1 self loop
        g_dis[1][i] = rsqrtf((float)(g_cnt[1][i] + 1));
    }
}

__global__ void k_scan1() {
    __shared__ int sh[1024];
    int which = blockIdx.y;
    int tid = threadIdx.x;
    int i = blockIdx.x * 1024 + tid;
    int v = (i < NN) ? g_cnt[which][i] : 0;
    sh[tid] = v; __syncthreads();
#pragma unroll
    for (int off = 1; off < 1024; off <<= 1) {
        int t = (tid >= off) ? sh[tid - off] : 0;
        __syncthreads();
        sh[tid] += t;
        __syncthreads();
    }
    if (i < NN) g_rowptr[which][i] = sh[tid] - v;     // exclusive
    if (tid == 1023) g_bsum[which][blockIdx.x] = sh[1023];
}

__global__ void k_scan2() {
    int which = threadIdx.x >> 5;   // 2 warps, warp w handles set w (serial in lane 0)
    if ((threadIdx.x & 31) == 0 && which < 2) {
        int s = 0;
        for (int i = 0; i < NB_SCAN; i++) { int t = g_bsum[which][i]; g_bsum[which][i] = s; s += t; }
    }
}

__global__ void k_scan3() {
    int which = blockIdx.y;
    int i = blockIdx.x * blockDim.x + threadIdx.x;
    if (i < NN) {
        int v = g_rowptr[which][i] + g_bsum[which][i >> 10];
        g_rowptr[which][i] = v;
        g_cur[which][i] = v;
    }
    if (i == 0) g_rowptr[which][NN] = EE;
}

__global__ void k_fill(const int* __restrict__ ei0, const float* __restrict__ ew0,
                       const int* __restrict__ ei1, const float* __restrict__ ew1) {
    int which = blockIdx.y;
    const int*   ei = which ? ei1 : ei0;
    const float* ew = which ? ew1 : ew0;
    int e = blockIdx.x * blockDim.x + threadIdx.x;
    if (e >= EE) return;
    int r = ei[e];
    int c = ei[EE + e];
    float w = ew[e];
    float dn   = g_dis[which][r] * g_dis[which][c];
    float einv = (w > 0.0f) ? fminf(rsqrtf(w), 1.0f) : 0.0f;
    int p = atomicAdd(&g_cur[which][c], 1);
    int4 pk;
    pk.x = r;
    pk.y = __float_as_int(dn);
    pk.z = __float_as_int(einv);
    pk.w = 0;
    g_epack[which][p] = pk;
}

// ---------------- build concat input (block per node, coalesced, fp16) ----------------
__global__ void k_build_xc(const float* __restrict__ x, const float* __restrict__ d2) {
    int n = blockIdx.x;
    int k = threadIdx.x;
    if (k >= KCH) return;
    float v = 0.0f;
    if (k < ENC)       v = x[n * ENC + k];
    else if (k < KIN)  v = d2[n * PI_ + (k - ENC)];
    g_xh[(size_t)n * KCH + k] = __float2half(v);
}

// ---------------- fused stage-1 weights: Wc[m] = Wsel[m%128] @ nodeWsel ----------------
__global__ void k_build_Wc(const float* __restrict__ W1a, const float* __restrict__ W1b,
                           const float* __restrict__ W2a, const float* __restrict__ W2b,
                           const float* __restrict__ nW1, const float* __restrict__ nW2) {
    int i = blockIdx.x * blockDim.x + threadIdx.x;
    if (i >= MH * KCH) return;
    int m = i / KCH, k = i - m * KCH;
    float v = 0.0f;
    if (k < KIN) {
        const float* Ws = (m < 128) ? W1a : (m < 256) ? W1b : (m < 384) ? W2a : W2b;
        const float* nW = (m < 256) ? nW1 : nW2;
        int mm = m & 127;
        float s = 0.0f;
#pragma unroll 8
        for (int j = 0; j < ENC; j++) s = fmaf(Ws[mm * ENC + j], nW[j * KIN + k], s);
        v = s;
    }
    g_wh1[i] = __float2half(v);
}

// stage-2 weights: g_wz[y][m][k]  y0: [W3a|W3b], y1: [W4a|W4b]  (m=out, k=0..255)
__global__ void k_build_wz(const float* __restrict__ W3a, const float* __restrict__ W3b,
                           const float* __restrict__ W4a, const float* __restrict__ W4b) {
    int i = blockIdx.x * blockDim.x + threadIdx.x;
    if (i >= 2 * 128 * 256) return;
    int y = i >> 15;
    int rem = i & 32767;
    int m = rem >> 8;
    int k = rem & 255;
    const float* Wa = y ? W4a : W3a;
    const float* Wb = y ? W4b : W3b;
    float v = (k < 128) ? Wa[m * 128 + k] : Wb[m * 128 + (k - 128)];
    g_wz[i] = __float2half(v);
}

// ---------------- stage-1 tensor-core GEMM: h[N,512] = xc[N,240] * W1[512,240]^T ----------------
__global__ __launch_bounds__(256, 2)
void k_gemm1() {
    const int K  = KCH;
    const int nk = K >> 4;

    __shared__ __align__(16) __half As[2][128 * 24];
    __shared__ __align__(16) __half Bs[2][128 * 24];

    const int tid  = threadIdx.x;
    const int lane = tid & 31;
    const int warp = tid >> 5;
    const int wm   = warp >> 2;
    const int wn   = warp & 3;
    const int bn   = blockIdx.x * 128;
    const int bm   = blockIdx.y * 128;

    const int  lrow = tid >> 1;
    const int  lcol = (tid & 1) * 8;
    const bool aval = (bn + lrow) < NN;
    const __half* Ab = g_xh + (size_t)(aval ? (bn + lrow) : 0) * K + lcol;
    const __half* Bb = g_wh1 + (size_t)(bm + lrow) * K + lcol;
    const int soff = lrow * 24 + lcol;

    const unsigned as_base = (unsigned)__cvta_generic_to_shared(&As[0][0]);
    const unsigned bs_base = (unsigned)__cvta_generic_to_shared(&Bs[0][0]);
    const unsigned a_off = ((wm * 64 + (lane & 15)) * 24 + (lane >> 4) * 8) * 2;
    const unsigned b_off = ((wn * 32 + (lane & 7)) * 24 + ((lane >> 3) & 1) * 8) * 2;
    const unsigned BUFB = 128 * 24 * 2;

    float c[4][4][4];
#pragma unroll
    for (int mi = 0; mi < 4; mi++)
#pragma unroll
        for (int ni = 0; ni < 4; ni++)
#pragma unroll
            for (int q = 0; q < 4; q++) c[mi][ni][q] = 0.0f;

    {
        uint4 av = make_uint4(0, 0, 0, 0);
        if (aval) av = *(const uint4*)Ab;
        uint4 bv = *(const uint4*)Bb;
        *(uint4*)&As[0][soff] = av;
        *(uint4*)&Bs[0][soff] = bv;
    }
    __syncthreads();

    for (int ks = 0; ks < nk; ks++) {
        const int buf = ks & 1;
        uint4 av = make_uint4(0, 0, 0, 0);
        uint4 bv = make_uint4(0, 0, 0, 0);
        const bool more = (ks + 1 < nk);
        if (more) {
            if (aval) av = *(const uint4*)(Ab + (ks + 1) * 16);
            bv = *(const uint4*)(Bb + (ks + 1) * 16);
        }
        unsigned a[4][4], b[4][2];
#pragma unroll
        for (int mi = 0; mi < 4; mi++)
            ldsm4(a[mi][0], a[mi][1], a[mi][2], a[mi][3],
                  as_base + buf * BUFB + a_off + mi * 16 * 48);
#pragma unroll
        for (int ni = 0; ni < 4; ni++)
            ldsm2(b[ni][0], b[ni][1],
                  bs_base + buf * BUFB + b_off + ni * 8 * 48);
#pragma unroll
        for (int mi = 0; mi < 4; mi++)
#pragma unroll
            for (int ni = 0; ni < 4; ni++)
                mma16816(c[mi][ni][0], c[mi][ni][1], c[mi][ni][2], c[mi][ni][3],
                         a[mi][0], a[mi][1], a[mi][2], a[mi][3],
                         b[ni][0], b[ni][1]);
        if (more) {
            *(uint4*)&As[buf ^ 1][soff] = av;
            *(uint4*)&Bs[buf ^ 1][soff] = bv;
        }
        __syncthreads();
    }

#pragma unroll
    for (int mi = 0; mi < 4; mi++) {
        int row = bn + wm * 64 + mi * 16 + (lane >> 2);
#pragma unroll
        for (int ni = 0; ni < 4; ni++) {
            int colh2 = ((bm + wn * 32 + ni * 8) >> 1) + (lane & 3);
            if (row < NN)
                g_hh[(size_t)row * (MH / 2) + colh2] =
                    __floats2half2_rn(c[mi][ni][0], c[mi][ni][1]);
            if (row + 8 < NN)
                g_hh[(size_t)(row + 8) * (MH / 2) + colh2] =
                    __floats2half2_rn(c[mi][ni][2], c[mi][ni][3]);
        }
    }
}

// ---------------- stage-1 aggregation: warp per node -> xm (fp16) ----------------
__global__ __launch_bounds__(256)
void k_agg1() {
    int n = blockIdx.x * 8 + (threadIdx.x >> 5);
    if (n >= NN) return;
    int lane = threadIdx.x & 31;

    const __half2* hr = g_hh + (size_t)n * (MH / 2) + lane * 2;

    float s0 = g_dis[0][n]; s0 *= s0;
    float s1 = g_dis[1][n]; s1 *= s1;

    float2 a0 = __half22float2(hr[0]),   a1 = __half22float2(hr[1]);
    float2 b0 = __half22float2(hr[64]),  b1 = __half22float2(hr[65]);
    float2 c0 = __half22float2(hr[128]), c1 = __half22float2(hr[129]);
    float2 d0 = __half22float2(hr[192]), d1 = __half22float2(hr[193]);

    float acc0[4] = { fmaf(s0, a0.x, b0.x), fmaf(s0, a0.y, b0.y),
                      fmaf(s0, a1.x, b1.x), fmaf(s0, a1.y, b1.y) };
    float acc1[4] = { fmaf(s1, c0.x, d0.x), fmaf(s1, c0.y, d0.y),
                      fmaf(s1, c1.x, d1.x), fmaf(s1, c1.y, d1.y) };

    {
        int beg = g_rowptr[0][n], end = g_rowptr[0][n + 1];
        for (int j = beg; j < end; j++) {
            int4 pk = g_epack[0][j];
            int   r    = pk.x;
            float dn   = __int_as_float(pk.y);
            float einv = __int_as_float(pk.z);
            const __half2* hp = g_hh + (size_t)r * (MH / 2) + lane * 2;
            float2 fa0 = __half22float2(hp[0]);
            float2 fa1 = __half22float2(hp[1]);
            float2 fb0 = __half22float2(hp[64]);
            float2 fb1 = __half22float2(hp[65]);
            acc0[0] = fmaf(dn, fa0.x, fmaf(einv, fb0.x, acc0[0]));
            acc0[1] = fmaf(dn, fa0.y, fmaf(einv, fb0.y, acc0[1]));
            acc0[2] = fmaf(dn, fa1.x, fmaf(einv, fb1.x, acc0[2]));
            acc0[3] = fmaf(dn, fa1.y, fmaf(einv, fb1.y, acc0[3]));
        }
    }
    {
        int beg = g_rowptr[1][n], end = g_rowptr[1][n + 1];
        for (int j = beg; j < end; j++) {
            int4 pk = g_epack[1][j];
            int   r    = pk.x;
            float dn   = __int_as_float(pk.y);
            float einv = __int_as_float(pk.z);
            const __half2* hp = g_hh + (size_t)r * (MH / 2) + 128 + lane * 2;
            float2 fa0 = __half22float2(hp[0]);
            float2 fa1 = __half22float2(hp[1]);
            float2 fb0 = __half22float2(hp[64]);
            float2 fb1 = __half22float2(hp[65]);
            acc1[0] = fmaf(dn, fa0.x, fmaf(einv, fb0.x, acc1[0]));
            acc1[1] = fmaf(dn, fa0.y, fmaf(einv, fb0.y, acc1[1]));
            acc1[2] = fmaf(dn, fa1.x, fmaf(einv, fb1.x, acc1[2]));
            acc1[3] = fmaf(dn, fa1.y, fmaf(einv, fb1.y, acc1[3]));
        }
    }

    __half2 h0 = __floats2half2_rn(0.5f * (fmaxf(acc0[0], 0.f) + fmaxf(acc1[0], 0.f)),
                                   0.5f * (fmaxf(acc0[1], 0.f) + fmaxf(acc1[1], 0.f)));
    __half2 h1 = __floats2half2_rn(0.5f * (fmaxf(acc0[2], 0.f) + fmaxf(acc1[2], 0.f)),
                                   0.5f * (fmaxf(acc0[3], 0.f) + fmaxf(acc1[3], 0.f)));
    uint2 st;
    st.x = *(unsigned*)&h0;
    st.y = *(unsigned*)&h1;
    *(uint2*)(g_xmh + (size_t)n * ENC + lane * 4) = st;
}

// ---------------- stage-2 pre-aggregation: gather xm once/edge -> [A0|B0|A1|B1] ----------------
__global__ __launch_bounds__(256)
void k_agg2pre() {
    int n = blockIdx.x * 8 + (threadIdx.x >> 5);
    if (n >= NN) return;
    int lane = threadIdx.x & 31;

    // self row
    uint2 sv = *(const uint2*)(g_xmh + (size_t)n * ENC + lane * 4);
    float2 x01 = __half22float2(*(__half2*)&sv.x);
    float2 x23 = __half22float2(*(__half2*)&sv.y);

    float s0 = g_dis[0][n]; s0 *= s0;
    float s1 = g_dis[1][n]; s1 *= s1;

    // A = sum dn*x (+ s^2*x self), B = sum einv*x (+ x self)
    float A0[4] = { s0 * x01.x, s0 * x01.y, s0 * x23.x, s0 * x23.y };
    float B0[4] = { x01.x, x01.y, x23.x, x23.y };
    float A1[4] = { s1 * x01.x, s1 * x01.y, s1 * x23.x, s1 * x23.y };
    float B1[4] = { x01.x, x01.y, x23.x, x23.y };

    {
        int beg = g_rowptr[0][n], end = g_rowptr[0][n + 1];
        for (int j = beg; j < end; j++) {
            int4 pk = g_epack[0][j];
            float dn   = __int_as_float(pk.y);
            float einv = __int_as_float(pk.z);
            uint2 v = *(const uint2*)(g_xmh + (size_t)pk.x * ENC + lane * 4);
            float2 v01 = __half22float2(*(__half2*)&v.x);
            float2 v23 = __half22float2(*(__half2*)&v.y);
            A0[0] = fmaf(dn, v01.x, A0[0]);  B0[0] = fmaf(einv, v01.x, B0[0]);
            A0[1] = fmaf(dn, v01.y, A0[1]);  B0[1] = fmaf(einv, v01.y, B0[1]);
            A0[2] = fmaf(dn, v23.x, A0[2]);  B0[2] = fmaf(einv, v23.x, B0[2]);
            A0[3] = fmaf(dn, v23.y, A0[3]);  B0[3] = fmaf(einv, v23.y, B0[3]);
        }
    }
    {
        int beg = g_rowptr[1][n], end = g_rowptr[1][n + 1];
        for (int j = beg; j < end; j++) {
            int4 pk = g_epack[1][j];
            float dn   = __int_as_float(pk.y);
            float einv = __int_as_float(pk.z);
            uint2 v = *(const uint2*)(g_xmh + (size_t)pk.x * ENC + lane * 4);
            float2 v01 = __half22float2(*(__half2*)&v.x);
            float2 v23 = __half22float2(*(__half2*)&v.y);
            A1[0] = fmaf(dn, v01.x, A1[0]);  B1[0] = fmaf(einv, v01.x, B1[0]);
            A1[1] = fmaf(dn, v01.y, A1[1]);  B1[1] = fmaf(einv, v01.y, B1[1]);
            A1[2] = fmaf(dn, v23.x, A1[2]);  B1[2] = fmaf(einv, v23.x, B1[2]);
            A1[3] = fmaf(dn, v23.y, A1[3]);  B1[3] = fmaf(einv, v23.y, B1[3]);
        }
    }

    __half* dst = g_agg + (size_t)n * 512 + lane * 4;
    auto st4 = [&](float* a, int off) {
        __half2 h0 = __floats2half2_rn(a[0], a[1]);
        __half2 h1 = __floats2half2_rn(a[2], a[3]);
        uint2 st;
        st.x = *(unsigned*)&h0;
        st.y = *(unsigned*)&h1;
        *(uint2*)(dst + off) = st;
    };
    st4(A0, 0);
    st4(B0, 128);
    st4(A1, 256);
    st4(B1, 384);
}

// ---------------- stage-2 GEMM: C_y[N,128] = agg_y[N,256] @ Wz_y[128,256]^T, relu ----------------
__global__ __launch_bounds__(256, 2)
void k_gemm2() {
    const int nk = 16;            // K = 256
    const int y  = blockIdx.y;

    __shared__ __align__(16) __half As[2][128 * 24];
    __shared__ __align__(16) __half Bs[2][128 * 24];

    const int tid  = threadIdx.x;
    const int lane = tid & 31;
    const int warp = tid >> 5;
    const int wm   = warp >> 2;
    const int wn   = warp & 3;
    const int bn   = blockIdx.x * 128;

    const int  lrow = tid >> 1;
    const int  lcol = (tid & 1) * 8;
    const bool aval = (bn + lrow) < NN;
    const __half* Ab = g_agg + (size_t)(aval ? (bn + lrow) : 0) * 512 + y * 256 + lcol;
    const __half* Bb = g_wz + y * (128 * 256) + lrow * 256 + lcol;
    const int soff = lrow * 24 + lcol;

    const unsigned as_base = (unsigned)__cvta_generic_to_shared(&As[0][0]);
    const unsigned bs_base = (unsigned)__cvta_generic_to_shared(&Bs[0][0]);
    const unsigned a_off = ((wm * 64 + (lane & 15)) * 24 + (lane >> 4) * 8) * 2;
    const unsigned b_off = ((wn * 32 + (lane & 7)) * 24 + ((lane >> 3) & 1) * 8) * 2;
    const unsigned BUFB = 128 * 24 * 2;

    float c[4][4][4];
#pragma unroll
    for (int mi = 0; mi < 4; mi++)
#pragma unroll
        for (int ni = 0; ni < 4; ni++)
#pragma unroll
            for (int q = 0; q < 4; q++) c[mi][ni][q] = 0.0f;

    {
        uint4 av = make_uint4(0, 0, 0, 0);
        if (aval) av = *(const uint4*)Ab;
        uint4 bv = *(const uint4*)Bb;
        *(uint4*)&As[0][soff] = av;
        *(uint4*)&Bs[0][soff] = bv;
    }
    __syncthreads();

    for (int ks = 0; ks < nk; ks++) {
        const int buf = ks & 1;
        uint4 av = make_uint4(0, 0, 0, 0);
        uint4 bv = make_uint4(0, 0, 0, 0);
        const bool more = (ks + 1 < nk);
        if (more) {
            if (aval) av = *(const uint4*)(Ab + (ks + 1) * 16);
            bv = *(const uint4*)(Bb + (ks + 1) * 16);
        }
        unsigned a[4][4], b[4][2];
#pragma unroll
        for (int mi = 0; mi < 4; mi++)
            ldsm4(a[mi][0], a[mi][1], a[mi][2], a[mi][3],
                  as_base + buf * BUFB + a_off + mi * 16 * 48);
#pragma unroll
        for (int ni = 0; ni < 4; ni++)
            ldsm2(b[ni][0], b[ni][1],
                  bs_base + buf * BUFB + b_off + ni * 8 * 48);
#pragma unroll
        for (int mi = 0; mi < 4; mi++)
#pragma unroll
            for (int ni = 0; ni < 4; ni++)
                mma16816(c[mi][ni][0], c[mi][ni][1], c[mi][ni][2], c[mi][ni][3],
                         a[mi][0], a[mi][1], a[mi][2], a[mi][3],
                         b[ni][0], b[ni][1]);
        if (more) {
            *(uint4*)&As[buf ^ 1][soff] = av;
            *(uint4*)&Bs[buf ^ 1][soff] = bv;
        }
        __syncthreads();
    }

    // relu + store fp16 to g_c12[n][y*128 + col]
    __half2* C = (__half2*)g_c12;
#pragma unroll
    for (int mi = 0; mi < 4; mi++) {
        int row = bn + wm * 64 + mi * 16 + (lane >> 2);
#pragma unroll
        for (int ni = 0; ni < 4; ni++) {
            int colh2 = ((y * 128 + wn * 32 + ni * 8) >> 1) + (lane & 3);
            if (row < NN)
                C[(size_t)row * 128 + colh2] =
                    __floats2half2_rn(fmaxf(c[mi][ni][0], 0.f), fmaxf(c[mi][ni][1], 0.f));
            if (row + 8 < NN)
                C[(size_t)(row + 8) * 128 + colh2] =
                    __floats2half2_rn(fmaxf(c[mi][ni][2], 0.f), fmaxf(c[mi][ni][3], 0.f));
        }
    }
}

// ---------------- final mix: out = 0.5*(C1 + C2) (already relu'd) ----------------
__global__ void k_mix(float* __restrict__ out) {
    int i = blockIdx.x * blockDim.x + threadIdx.x;
    if (i >= NN * 32) return;
    int n = i >> 5, lane = i & 31;
    const __half2* C = (const __half2*)g_c12 + (size_t)n * 128;
    float2 p0 = __half22float2(C[lane * 2]);
    float2 p1 = __half22float2(C[lane * 2 + 1]);
    float2 q0 = __half22float2(C[64 + lane * 2]);
    float2 q1 = __half22float2(C[64 + lane * 2 + 1]);
    float4 o = make_float4(0.5f * (p0.x + q0.x), 0.5f * (p0.y + q0.y),
                           0.5f * (p1.x + q1.x), 0.5f * (p1.y + q1.y));
    *(float4*)(out + (size_t)n * EMB + lane * 4) = o;
}

// ---------------- launch ----------------
extern "C" void kernel_launch(void* const* d_in, const int* in_sizes, int n_in,
                              void* d_out, int out_size) {
    const float* x    = (const float*)d_in[0];
    const float* d2an = (const float*)d_in[1];
    const int*   ei0  = (const int*)  d_in[2];
    const float* ew0  = (const float*)d_in[3];
    const int*   ei1  = (const int*)  d_in[4];
    const float* ew1  = (const float*)d_in[5];
    const float* nW1  = (const float*)d_in[6];
    const float* nW2  = (const float*)d_in[7];
    const float* W1a  = (const float*)d_in[8];
    const float* W1b  = (const float*)d_in[9];
    const float* W2a  = (const float*)d_in[10];
    const float* W2b  = (const float*)d_in[11];
    const float* W3a  = (const float*)d_in[12];
    const float* W3b  = (const float*)d_in[13];
    const float* W4a  = (const float*)d_in[14];
    const float* W4b  = (const float*)d_in[15];
    float* out = (float*)d_out;

    const int TB = 256;
    const int ng = (NN + TB - 1) / TB;
    const int eg = (EE + TB - 1) / TB;

    // ---- CSR build ----
    k_zero_cnt<<<ng, TB>>>();
    k_hist    <<<eg, TB>>>(ei0, ei1);
    k_dis_k   <<<ng, TB>>>();
    k_scan1<<<dim3(NB_SCAN, 2), 1024>>>();
    k_scan2<<<1, 64>>>();
    k_scan3<<<dim3(ng, 2), TB>>>();
    k_fill <<<dim3(eg, 2), TB>>>(ei0, ew0, ei1, ew1);

    // ---- weights / inputs ----
    k_build_xc<<<NN, 256>>>(x, d2an);
    k_build_Wc<<<(MH * KCH + TB - 1) / TB, TB>>>(W1a, W1b, W2a, W2b, nW1, nW2);
    k_build_wz<<<(2 * 128 * 256 + TB - 1) / TB, TB>>>(W3a, W3b, W4a, W4b);

    const int ag = (NN + 7) / 8;

    // ---- stage 1 ----
    k_gemm1<<<dim3((NN + 127) / 128, MH / 128), 256>>>();
    k_agg1 <<<ag, 256>>>();                          // -> g_xmh (fp16)

    // ---- stage 2 (pre-aggregation) ----
    k_agg2pre<<<ag, 256>>>();                        // -> g_agg [A0|B0|A1|B1]
    k_gemm2  <<<dim3((NN + 127) / 128, 2), 256>>>(); // -> g_c12 (relu'd halves)
    k_mix    <<<(NN * 32 + TB - 1) / TB, TB>>>(out); // -> d_out
}

// round 8
// speedup vs baseline: 1.2117x; 1.2117x over previous
#include <cuda_runtime.h>
#include <cuda_fp16.h>
#include <cstdint>
#include <math.h>

#define NN   100000
#define EE   1600000
#define ENC  128
#define PI_  98
#define KIN  226          // ENC + PI
#define KCH  240          // KIN padded to multiple of 16
#define MH   512          // 4 stacked [*,128] outputs
#define EMB  128
#define NB_SCAN 98        // ceil(NN/1024)

// ---------------- scratch (static device globals; no allocation) ----------------
__device__ __half   g_xh [(size_t)NN * KCH];     // concat(x,d2an) fp16
__device__ __half   g_wh1[MH * KCH];             // stage-1 fused weights fp16
__device__ __half   g_wh2[MH * ENC];             // stage-2 stacked weights fp16
__device__ __half   g_xmh[(size_t)NN * ENC];     // stage-1 result fp16
__device__ __half2  g_hh [(size_t)NN * (MH/2)];  // GEMM output h (fp16)

// CSR (per edge set)
__device__ int     g_cnt   [2][NN];
__device__ int     g_rowptr[2][NN + 1];
__device__ int     g_cur   [2][NN];
__device__ int     g_bsum  [2][NB_SCAN];
__device__ float   g_dis   [2][NN];
__device__ uint2   g_epk   [2][EE];              // {src, half2(dn,einv)}

// ---------------- mma helpers ----------------
__device__ __forceinline__ void ldsm4(unsigned &r0, unsigned &r1, unsigned &r2, unsigned &r3,
                                      unsigned addr) {
    asm volatile("ldmatrix.sync.aligned.m8n8.x4.shared.b16 {%0,%1,%2,%3}, [%4];"
                 : "=r"(r0), "=r"(r1), "=r"(r2), "=r"(r3) : "r"(addr));
}
__device__ __forceinline__ void ldsm2(unsigned &r0, unsigned &r1, unsigned addr) {
    asm volatile("ldmatrix.sync.aligned.m8n8.x2.shared.b16 {%0,%1}, [%2];"
                 : "=r"(r0), "=r"(r1) : "r"(addr));
}
__device__ __forceinline__ void mma16816(float &c0, float &c1, float &c2, float &c3,
                                         unsigned a0, unsigned a1, unsigned a2, unsigned a3,
                                         unsigned b0, unsigned b1) {
    asm volatile("mma.sync.aligned.m16n8k16.row.col.f32.f16.f16.f32 "
                 "{%0,%1,%2,%3}, {%4,%5,%6,%7}, {%8,%9}, {%0,%1,%2,%3};"
                 : "+f"(c0), "+f"(c1), "+f"(c2), "+f"(c3)
                 : "r"(a0), "r"(a1), "r"(a2), "r"(a3), "r"(b0), "r"(b1));
}

// ---------------- CSR build ----------------
__global__ void k_zero_cnt() {
    int i = blockIdx.x * blockDim.x + threadIdx.x;
    if (i < NN) { g_cnt[0][i] = 0; g_cnt[1][i] = 0; }
}

__global__ void k_hist(const int* __restrict__ ei0, const int* __restrict__ ei1) {
    int e = blockIdx.x * blockDim.x + threadIdx.x;
    if (e < EE) {
        atomicAdd(&g_cnt[0][ei0[EE + e]], 1);
        atomicAdd(&g_cnt[1][ei1[EE + e]], 1);
    }
}

__global__ void k_dis_k() {
    int i = blockIdx.x * blockDim.x + threadIdx.x;
    if (i < NN) {
        g_dis[0][i] = rsqrtf((float)(g_cnt[0][i] + 1));   // +1 self loop
        g_dis[1][i] = rsqrtf((float)(g_cnt[1][i] + 1));
    }
}

__global__ void k_scan1() {
    __shared__ int sh[1024];
    int which = blockIdx.y;
    int tid = threadIdx.x;
    int i = blockIdx.x * 1024 + tid;
    int v = (i < NN) ? g_cnt[which][i] : 0;
    sh[tid] = v; __syncthreads();
#pragma unroll
    for (int off = 1; off < 1024; off <<= 1) {
        int t = (tid >= off) ? sh[tid - off] : 0;
        __syncthreads();
        sh[tid] += t;
        __syncthreads();
    }
    if (i < NN) g_rowptr[which][i] = sh[tid] - v;     // exclusive
    if (tid == 1023) g_bsum[which][blockIdx.x] = sh[1023];
}

__global__ void k_scan2() {
    int which = threadIdx.x >> 5;
    if ((threadIdx.x & 31) == 0 && which < 2) {
        int s = 0;
        for (int i = 0; i < NB_SCAN; i++) { int t = g_bsum[which][i]; g_bsum[which][i] = s; s += t; }
    }
}

__global__ void k_scan3() {
    int which = blockIdx.y;
    int i = blockIdx.x * blockDim.x + threadIdx.x;
    if (i < NN) {
        int v = g_rowptr[which][i] + g_bsum[which][i >> 10];
        g_rowptr[which][i] = v;
        g_cur[which][i] = v;
    }
    if (i == 0) g_rowptr[which][NN] = EE;
}

__global__ void k_fill(const int* __restrict__ ei0, const float* __restrict__ ew0,
                       const int* __restrict__ ei1, const float* __restrict__ ew1) {
    int which = blockIdx.y;
    const int*   ei = which ? ei1 : ei0;
    const float* ew = which ? ew1 : ew0;
    int e = blockIdx.x * blockDim.x + threadIdx.x;
    if (e >= EE) return;
    int r = ei[e];
    int c = ei[EE + e];
    float w = ew[e];
    float dn   = g_dis[which][r] * g_dis[which][c];
    float einv = (w > 0.0f) ? fminf(rsqrtf(w), 1.0f) : 0.0f;
    int p = atomicAdd(&g_cur[which][c], 1);
    __half2 de = __floats2half2_rn(dn, einv);
    uint2 pk;
    pk.x = (unsigned)r;
    pk.y = *(unsigned*)&de;
    g_epk[which][p] = pk;
}

// ---------------- build concat input: warp per node, 8 elems/thread ----------------
__global__ void k_build_xc(const float* __restrict__ x, const float* __restrict__ d2) {
    int n = blockIdx.x * 8 + (threadIdx.x >> 5);
    if (n >= NN) return;
    int lane = threadIdx.x & 31;
    int k0 = lane * 8;
    if (k0 >= KCH) return;                       // lanes 30,31 idle
    __half h[8];
    if (k0 + 8 <= ENC) {
        float4 a = *(const float4*)(x + (size_t)n * ENC + k0);
        float4 b = *(const float4*)(x + (size_t)n * ENC + k0 + 4);
        h[0] = __float2half(a.x); h[1] = __float2half(a.y);
        h[2] = __float2half(a.z); h[3] = __float2half(a.w);
        h[4] = __float2half(b.x); h[5] = __float2half(b.y);
        h[6] = __float2half(b.z); h[7] = __float2half(b.w);
    } else {
#pragma unroll
        for (int i = 0; i < 8; i++) {
            int k = k0 + i;
            float v = 0.0f;
            if (k < KIN) v = d2[(size_t)n * PI_ + (k - ENC)];
            h[i] = __float2half(v);
        }
    }
    *(uint4*)(g_xh + (size_t)n * KCH + k0) = *(uint4*)h;
}

// ---------------- fused weights: Wc[m] = Wsel[m%128] @ nodeWsel (fp16 out) ----------------
__global__ void k_build_Wc(const float* __restrict__ W1a, const float* __restrict__ W1b,
                           const float* __restrict__ W2a, const float* __restrict__ W2b,
                           const float* __restrict__ nW1, const float* __restrict__ nW2) {
    int i = blockIdx.x * blockDim.x + threadIdx.x;
    if (i >= MH * KCH) return;
    int m = i / KCH, k = i - m * KCH;
    float v = 0.0f;
    if (k < KIN) {
        const float* Ws = (m < 128) ? W1a : (m < 256) ? W1b : (m < 384) ? W2a : W2b;
        const float* nW = (m < 256) ? nW1 : nW2;
        int mm = m & 127;
        float s = 0.0f;
#pragma unroll 8
        for (int j = 0; j < ENC; j++) s = fmaf(Ws[mm * ENC + j], nW[j * KIN + k], s);
        v = s;
    }
    g_wh1[i] = __float2half(v);
}

__global__ void k_build_Wc2(const float* __restrict__ W3a, const float* __restrict__ W3b,
                            const float* __restrict__ W4a, const float* __restrict__ W4b) {
    int i = blockIdx.x * blockDim.x + threadIdx.x;
    if (i >= MH * ENC) return;
    int m = i / ENC, k = i - m * ENC;
    const float* Ws = (m < 128) ? W3a : (m < 256) ? W3b : (m < 384) ? W4a : W4b;
    g_wh2[i] = __float2half(Ws[(m & 127) * ENC + k]);
}

// ---------------- tensor-core GEMM: C[N,512] = A[N,K] * W[512,K]^T ----------------
__global__ __launch_bounds__(256, 2)
void k_gemm_mma(int stage) {
    const __half* __restrict__ A = stage ? g_xmh : g_xh;
    const __half* __restrict__ B = stage ? g_wh2 : g_wh1;
    const int K  = stage ? ENC : KCH;
    const int nk = K >> 4;

    __shared__ __align__(16) __half As[2][128 * 24];
    __shared__ __align__(16) __half Bs[2][128 * 24];

    const int tid  = threadIdx.x;
    const int lane = tid & 31;
    const int warp = tid >> 5;
    const int wm   = warp >> 2;
    const int wn   = warp & 3;
    const int bn   = blockIdx.x * 128;
    const int bm   = blockIdx.y * 128;

    const int  lrow = tid >> 1;
    const int  lcol = (tid & 1) * 8;
    const bool aval = (bn + lrow) < NN;
    const __half* Ab = A + (size_t)(aval ? (bn + lrow) : 0) * K + lcol;
    const __half* Bb = B + (size_t)(bm + lrow) * K + lcol;
    const int soff = lrow * 24 + lcol;

    const unsigned as_base = (unsigned)__cvta_generic_to_shared(&As[0][0]);
    const unsigned bs_base = (unsigned)__cvta_generic_to_shared(&Bs[0][0]);
    const unsigned a_off = ((wm * 64 + (lane & 15)) * 24 + (lane >> 4) * 8) * 2;
    const unsigned b_off = ((wn * 32 + (lane & 7)) * 24 + ((lane >> 3) & 1) * 8) * 2;
    const unsigned BUFB = 128 * 24 * 2;

    float c[4][4][4];
#pragma unroll
    for (int mi = 0; mi < 4; mi++)
#pragma unroll
        for (int ni = 0; ni < 4; ni++)
#pragma unroll
            for (int q = 0; q < 4; q++) c[mi][ni][q] = 0.0f;

    {
        uint4 av = make_uint4(0, 0, 0, 0);
        if (aval) av = *(const uint4*)Ab;
        uint4 bv = *(const uint4*)Bb;
        *(uint4*)&As[0][soff] = av;
        *(uint4*)&Bs[0][soff] = bv;
    }
    __syncthreads();

    for (int ks = 0; ks < nk; ks++) {
        const int buf = ks & 1;
        uint4 av = make_uint4(0, 0, 0, 0);
        uint4 bv = make_uint4(0, 0, 0, 0);
        const bool more = (ks + 1 < nk);
        if (more) {
            if (aval) av = *(const uint4*)(Ab + (ks + 1) * 16);
            bv = *(const uint4*)(Bb + (ks + 1) * 16);
        }
        unsigned a[4][4], b[4][2];
#pragma unroll
        for (int mi = 0; mi < 4; mi++)
            ldsm4(a[mi][0], a[mi][1], a[mi][2], a[mi][3],
                  as_base + buf * BUFB + a_off + mi * 16 * 48);
#pragma unroll
        for (int ni = 0; ni < 4; ni++)
            ldsm2(b[ni][0], b[ni][1],
                  bs_base + buf * BUFB + b_off + ni * 8 * 48);
#pragma unroll
        for (int mi = 0; mi < 4; mi++)
#pragma unroll
            for (int ni = 0; ni < 4; ni++)
                mma16816(c[mi][ni][0], c[mi][ni][1], c[mi][ni][2], c[mi][ni][3],
                         a[mi][0], a[mi][1], a[mi][2], a[mi][3],
                         b[ni][0], b[ni][1]);
        if (more) {
            *(uint4*)&As[buf ^ 1][soff] = av;
            *(uint4*)&Bs[buf ^ 1][soff] = bv;
        }
        __syncthreads();
    }

#pragma unroll
    for (int mi = 0; mi < 4; mi++) {
        int row = bn + wm * 64 + mi * 16 + (lane >> 2);
#pragma unroll
        for (int ni = 0; ni < 4; ni++) {
            int colh2 = ((bm + wn * 32 + ni * 8) >> 1) + (lane & 3);
            if (row < NN)
                g_hh[(size_t)row * (MH / 2) + colh2] =
                    __floats2half2_rn(c[mi][ni][0], c[mi][ni][1]);
            if (row + 8 < NN)
                g_hh[(size_t)(row + 8) * (MH / 2) + colh2] =
                    __floats2half2_rn(c[mi][ni][2], c[mi][ni][3]);
        }
    }
}

// ---------------- fused aggregation: warp per node, both edge sets, relu+mix ----------------
__global__ __launch_bounds__(256)
void k_agg(float* __restrict__ dst_ext, int use_ext) {
    int n = blockIdx.x * 8 + (threadIdx.x >> 5);
    if (n >= NN) return;
    int lane = threadIdx.x & 31;

    const __half2* hr = g_hh + (size_t)n * (MH / 2) + lane * 2;

    float s0 = g_dis[0][n]; s0 *= s0;
    float s1 = g_dis[1][n]; s1 *= s1;

    float2 a0 = __half22float2(hr[0]),   a1 = __half22float2(hr[1]);
    float2 b0 = __half22float2(hr[64]),  b1 = __half22float2(hr[65]);
    float2 c0 = __half22float2(hr[128]), c1 = __half22float2(hr[129]);
    float2 d0 = __half22float2(hr[192]), d1 = __half22float2(hr[193]);

    float acc0[4] = { fmaf(s0, a0.x, b0.x), fmaf(s0, a0.y, b0.y),
                      fmaf(s0, a1.x, b1.x), fmaf(s0, a1.y, b1.y) };
    float acc1[4] = { fmaf(s1, c0.x, d0.x), fmaf(s1, c0.y, d0.y),
                      fmaf(s1, c1.x, d1.x), fmaf(s1, c1.y, d1.y) };

    {
        int beg = g_rowptr[0][n], end = g_rowptr[0][n + 1];
#pragma unroll 4
        for (int j = beg; j < end; j++) {
            uint2 pk = g_epk[0][j];
            float2 de = __half22float2(*(__half2*)&pk.y);
            const __half2* hp = g_hh + (size_t)pk.x * (MH / 2) + lane * 2;
            float2 fa0 = __half22float2(hp[0]);
            float2 fa1 = __half22float2(hp[1]);
            float2 fb0 = __half22float2(hp[64]);
            float2 fb1 = __half22float2(hp[65]);
            acc0[0] = fmaf(de.x, fa0.x, fmaf(de.y, fb0.x, acc0[0]));
            acc0[1] = fmaf(de.x, fa0.y, fmaf(de.y, fb0.y, acc0[1]));
            acc0[2] = fmaf(de.x, fa1.x, fmaf(de.y, fb1.x, acc0[2]));
            acc0[3] = fmaf(de.x, fa1.y, fmaf(de.y, fb1.y, acc0[3]));
        }
    }
    {
        int beg = g_rowptr[1][n], end = g_rowptr[1][n + 1];
#pragma unroll 4
        for (int j = beg; j < end; j++) {
            uint2 pk = g_epk[1][j];
            float2 de = __half22float2(*(__half2*)&pk.y);
            const __half2* hp = g_hh + (size_t)pk.x * (MH / 2) + 128 + lane * 2;
            float2 fa0 = __half22float2(hp[0]);
            float2 fa1 = __half22float2(hp[1]);
            float2 fb0 = __half22float2(hp[64]);
            float2 fb1 = __half22float2(hp[65]);
            acc1[0] = fmaf(de.x, fa0.x, fmaf(de.y, fb0.x, acc1[0]));
            acc1[1] = fmaf(de.x, fa0.y, fmaf(de.y, fb0.y, acc1[1]));
            acc1[2] = fmaf(de.x, fa1.x, fmaf(de.y, fb1.x, acc1[2]));
            acc1[3] = fmaf(de.x, fa1.y, fmaf(de.y, fb1.y, acc1[3]));
        }
    }

    float4 o = make_float4(
        0.5f * (fmaxf(acc0[0], 0.f) + fmaxf(acc1[0], 0.f)),
        0.5f * (fmaxf(acc0[1], 0.f) + fmaxf(acc1[1], 0.f)),
        0.5f * (fmaxf(acc0[2], 0.f) + fmaxf(acc1[2], 0.f)),
        0.5f * (fmaxf(acc0[3], 0.f) + fmaxf(acc1[3], 0.f)));

    if (use_ext) {
        *(float4*)(dst_ext + (size_t)n * EMB + lane * 4) = o;
    } else {
        __half2 h0 = __floats2half2_rn(o.x, o.y);
        __half2 h1 = __floats2half2_rn(o.z, o.w);
        uint2 st;
        st.x = *(unsigned*)&h0;
        st.y = *(unsigned*)&h1;
        *(uint2*)(g_xmh + (size_t)n * ENC + lane * 4) = st;
    }
}

// ---------------- launch ----------------
extern "C" void kernel_launch(void* const* d_in, const int* in_sizes, int n_in,
                              void* d_out, int out_size) {
    const float* x    = (const float*)d_in[0];
    const float* d2an = (const float*)d_in[1];
    const int*   ei0  = (const int*)  d_in[2];
    const float* ew0  = (const float*)d_in[3];
    const int*   ei1  = (const int*)  d_in[4];
    const float* ew1  = (const float*)d_in[5];
    const float* nW1  = (const float*)d_in[6];
    const float* nW2  = (const float*)d_in[7];
    const float* W1a  = (const float*)d_in[8];
    const float* W1b  = (const float*)d_in[9];
    const float* W2a  = (const float*)d_in[10];
    const float* W2b  = (const float*)d_in[11];
    const float* W3a  = (const float*)d_in[12];
    const float* W3b  = (const float*)d_in[13];
    const float* W4a  = (const float*)d_in[14];
    const float* W4b  = (const float*)d_in[15];
    float* out = (float*)d_out;

    const int TB = 256;
    const int ng = (NN + TB - 1) / TB;
    const int eg = (EE + TB - 1) / TB;

    // ---- CSR build ----
    k_zero_cnt<<<ng, TB>>>();
    k_hist    <<<eg, TB>>>(ei0, ei1);
    k_dis_k   <<<ng, TB>>>();
    k_scan1<<<dim3(NB_SCAN, 2), 1024>>>();
    k_scan2<<<1, 64>>>();
    k_scan3<<<dim3(ng, 2), TB>>>();
    k_fill <<<dim3(eg, 2), TB>>>(ei0, ew0, ei1, ew1);

    // ---- weights / inputs ----
    k_build_xc <<<(NN + 7) / 8, 256>>>(x, d2an);
    k_build_Wc <<<(MH * KCH + TB - 1) / TB, TB>>>(W1a, W1b, W2a, W2b, nW1, nW2);
    k_build_Wc2<<<(MH * ENC + TB - 1) / TB, TB>>>(W3a, W3b, W4a, W4b);

    dim3 gg((NN + 127) / 128, MH / 128);
    const int ag = (NN + 7) / 8;

    // ---- stage 1 ----
    k_gemm_mma<<<gg, 256>>>(0);
    k_agg     <<<ag, 256>>>(nullptr, 0);   // -> g_xmh (fp16)

    // ---- stage 2 ----
    k_gemm_mma<<<gg, 256>>>(1);
    k_agg     <<<ag, 256>>>(out, 1);       // -> d_out
}